// round 5
// baseline (speedup 1.0000x reference)
#include <cuda_runtime.h>
#include <cuda_bf16.h>
#include <cstdint>

// LSTM B=65536, T=7, H=128. Fused recurrence, warp-level mma.sync bf16->f32.
// CTA = 256 thr / 8 warps, 32 batch rows as TWO 16-row tiles, skew-pipelined:
//   MMA(t1,s) ; epi(t0,s) ; sync ; MMA(t0,s+1) ; epi(t1,s) ; sync
// so each epilogue overlaps the other tile's tensor drain.
// W_hh (B operand) fragments live in REGISTERS for the whole kernel (128 regs),
// loaded once from gmem in mma fragment layout -> zero per-step B LDS traffic,
// no W SMEM tile. A (h) is bf16 in SMEM, double-buffered per tile, ldmatrix.
// Gate regroup via lane-pair shfl (W cols permuted logically: col j = u*4+g).

#define T 7
#define ROWS_CTA 32
#define NTH 256
#define HSTR 136                       // 17x16B pitch -> conflict-free ldmatrix

#define HB_BYTES (16 * HSTR * 2)       // 4352 per 16-row bf16 buffer
#define HB_OFF(tile, par) (((tile) * 2 + (par)) * HB_BYTES)
#define F32_OFF (4 * HB_BYTES)         // 17408
#define F_BIAS 0                       // 512 (permuted j=u*4+g)
#define F_WIH  512                     // 512
#define F_WOUT 1024                    // 128
#define F_XS   1152                    // 32 rows x 8 slots
#define F_PRED 1408                    // 2 x (32 rows x 8 warps)
#define F_COUNT 1920
#define SMEM_TOTAL (F32_OFF + F_COUNT * 4)   // 25088 bytes

static __device__ __forceinline__ uint32_t smem_u32(const void* p) {
    uint32_t a;
    asm("{ .reg .u64 t; cvta.to.shared.u64 t, %1; cvt.u32.u64 %0, t; }"
        : "=r"(a) : "l"(p));
    return a;
}
static __device__ __forceinline__ float tanh_fast(float v) {
    float y; asm("tanh.approx.f32 %0, %1;" : "=f"(y) : "f"(v)); return y;
}
static __device__ __forceinline__ float sigmoid_fast(float v) {
    return 0.5f * tanh_fast(0.5f * v) + 0.5f;
}
static __device__ __forceinline__ uint32_t pack_bf16x2(float lo, float hi) {
    uint32_t r;
    asm("cvt.rn.bf16x2.f32 %0, %1, %2;" : "=r"(r) : "f"(hi), "f"(lo));
    return r;
}

#define LDSM_X4(r0, r1, r2, r3, addr) \
    asm volatile("ldmatrix.sync.aligned.m8n8.x4.shared.b16 {%0,%1,%2,%3}, [%4];" \
        : "=r"(r0), "=r"(r1), "=r"(r2), "=r"(r3) : "r"(addr))

#define MMA16816(D, A0, A1, A2, A3, B0, B1) \
    asm volatile("mma.sync.aligned.m16n8k16.row.col.f32.bf16.bf16.f32 " \
        "{%0,%1,%2,%3}, {%4,%5,%6,%7}, {%8,%9}, {%0,%1,%2,%3};" \
        : "+f"((D)[0]), "+f"((D)[1]), "+f"((D)[2]), "+f"((D)[3]) \
        : "r"(A0), "r"(A1), "r"(A2), "r"(A3), "r"(B0), "r"(B1))

// One 16-row tile step: gates[16,64-slice] += h_tile @ W-slice^T, K=128.
static __device__ __forceinline__ void mma_tile(float acc[8][4], uint32_t ha,
                                                const uint32_t Bf[8][8][2]) {
#pragma unroll
    for (int nt = 0; nt < 8; nt++)
#pragma unroll
        for (int e = 0; e < 4; e++) acc[nt][e] = 0.0f;
#pragma unroll
    for (int kc = 0; kc < 8; kc++) {
        uint32_t a0, a1, a2, a3;
        LDSM_X4(a0, a1, a2, a3, ha + kc * 32);
#pragma unroll
        for (int nt = 0; nt < 8; nt++)
            MMA16816(acc[nt], a0, a1, a2, a3, Bf[nt][kc][0], Bf[nt][kc][1]);
    }
}

__global__ __launch_bounds__(NTH, 1)
void lstm_mma_kernel(const float* __restrict__ x,
                     const float* __restrict__ x0,
                     const float* __restrict__ W_ih,
                     const float* __restrict__ W_hh,
                     const float* __restrict__ b_ih,
                     const float* __restrict__ b_hh,
                     const float* __restrict__ W_out,
                     const float* __restrict__ b_out,
                     float* __restrict__ out)
{
    extern __shared__ char smem[];
    const uint32_t sb = smem_u32(smem);
    float* f32s = (float*)(smem + F32_OFF);

    const int tid  = threadIdx.x;
    const int wid  = tid >> 5;        // 0..7, owns permuted cols wid*64..+63
    const int lane = tid & 31;
    const int q    = lane & 3;
    const int par  = q & 1;           // gate-pair parity -> row r / r+8 after swap
    const int hu   = q >> 1;          // unit-within-pair
    const int rowBase = blockIdx.x * ROWS_CTA;

    // ---- B fragments from gmem, mma.sync m16n8k16 col-major layout ----
    // b0: k=(kc*16 + q*2 +{0,1}), n = lane>>2 ; b1: same n, k+8.
    // permuted col j -> W_hh row src=(j&3)*128 + (j>>2); k contiguous in W_hh.
    uint32_t Bf[8][8][2];
#pragma unroll
    for (int nt = 0; nt < 8; nt++) {
        const int j   = wid * 64 + nt * 8 + (lane >> 2);
        const int src = (j & 3) * 128 + (j >> 2);
        const float* wr = W_hh + src * 128;
#pragma unroll
        for (int kc = 0; kc < 8; kc++) {
            float2 lo = *(const float2*)(wr + kc * 16 + q * 2);
            float2 hi = *(const float2*)(wr + kc * 16 + 8 + q * 2);
            Bf[nt][kc][0] = pack_bf16x2(lo.x, lo.y);
            Bf[nt][kc][1] = pack_bf16x2(hi.x, hi.y);
        }
    }

    // ---- SMEM staging: zero h buffers, permuted bias/W_ih, W_out, x slots ----
    for (int i = tid; i < F32_OFF / 4; i += NTH)
        *(uint32_t*)(smem + i * 4) = 0u;
    for (int i = tid; i < 512; i += NTH) {
        int u = i >> 2, g = i & 3, src = g * 128 + u;
        f32s[F_BIAS + i] = b_ih[src] + b_hh[src];
        f32s[F_WIH + i]  = W_ih[src];
    }
    if (tid < 128) f32s[F_WOUT + tid] = W_out[tid];
    {   // tid exactly covers 32 rows x 8 slots
        int row = tid >> 3, sl = tid & 7;
        f32s[F_XS + tid] = (sl == 0) ? x0[rowBase + row]
                                     : x[(rowBase + row) * T + (sl - 1)];
    }
    __syncthreads();

    const float bout = b_out[0];
    const uint32_t aOff = (uint32_t)(((lane & 15) * HSTR + ((lane >> 4) & 1) * 8) * 2);
    const int rowIn = (lane >> 2) + par * 8;     // row within 16-row tile

    float cst[2][8];
#pragma unroll
    for (int t = 0; t < 2; t++)
#pragma unroll
        for (int nt = 0; nt < 8; nt++) cst[t][nt] = 0.0f;

    float acc0[8][4], acc1[8][4];

    // ---- epilogue for one tile ----
    auto epi = [&](int tile, float (&acc)[8][4], float* cs, int s) {
        const int grow = tile * 16 + rowIn;                 // 0..31
        const float xv = f32s[F_XS + grow * 8 + s];
        const uint32_t hb = HB_OFF(tile, (s + 1) & 1);
        float pred = 0.0f;
#pragma unroll
        for (int nt = 0; nt < 8; nt++) {
            float s0 = par ? acc[nt][0] : acc[nt][2];
            float s1 = par ? acc[nt][1] : acc[nt][3];
            float r0 = __shfl_xor_sync(0xffffffffu, s0, 1);
            float r1 = __shfl_xor_sync(0xffffffffu, s1, 1);
            float gi = par ? r0 : acc[nt][0];
            float gf = par ? r1 : acc[nt][1];
            float gg = par ? acc[nt][2] : r0;
            float go = par ? acc[nt][3] : r1;

            const int u = wid * 16 + nt * 2 + hu;           // unit 0..127
            const float4 b4 = *(const float4*)&f32s[F_BIAS + u * 4];
            const float4 w4 = *(const float4*)&f32s[F_WIH + u * 4];
            gi += b4.x + xv * w4.x;
            gf += b4.y + xv * w4.y;
            gg += b4.z + xv * w4.z;
            go += b4.w + xv * w4.w;

            float ig = sigmoid_fast(gi);
            float fg = sigmoid_fast(gf);
            float g_ = tanh_fast(gg);
            float og = sigmoid_fast(go);
            float cn = fg * cs[nt] + ig * g_;
            cs[nt] = cn;
            float hn = og * tanh_fast(cn);
            pred += hn * f32s[F_WOUT + u];

            float hx = __shfl_xor_sync(0xffffffffu, hn, 2);  // partner unit u^1
            if (hu == 0)
                *(uint32_t*)(smem + hb + (uint32_t)((rowIn * HSTR + wid * 16 + nt * 2) * 2)) =
                    pack_bf16x2(hn, hx);
        }
        pred += __shfl_xor_sync(0xffffffffu, pred, 2);       // combine unit halves
        if (q < 2) f32s[F_PRED + (s & 1) * 256 + grow * 8 + wid] = pred;
    };

    // ---- skew-pipelined recurrence ----
    mma_tile(acc0, sb + HB_OFF(0, 0) + aOff, Bf);
    for (int s = 0; s < T; s++) {
        mma_tile(acc1, sb + HB_OFF(1, s & 1) + aOff, Bf);
        epi(0, acc0, cst[0], s);                    // overlaps tile1 drain
        __syncthreads();                            // publish h0[nxt], pred0
        if (s + 1 < T)
            mma_tile(acc0, sb + HB_OFF(0, (s + 1) & 1) + aOff, Bf);
        epi(1, acc1, cst[1], s);                    // overlaps tile0 drain
        __syncthreads();                            // publish h1[nxt], pred1
        if (tid < ROWS_CTA) {
            float p = bout;
            const float* pp = &f32s[F_PRED + (s & 1) * 256 + tid * 8];
#pragma unroll
            for (int w = 0; w < 8; w++) p += pp[w];
            out[(rowBase + tid) * T + s] = p;
        }
    }
}

extern "C" void kernel_launch(void* const* d_in, const int* in_sizes, int n_in,
                              void* d_out, int out_size)
{
    const float* x     = (const float*)d_in[0];
    const float* x0    = (const float*)d_in[1];
    const float* W_ih  = (const float*)d_in[2];
    const float* W_hh  = (const float*)d_in[3];
    const float* b_ih  = (const float*)d_in[4];
    const float* b_hh  = (const float*)d_in[5];
    const float* W_out = (const float*)d_in[6];
    const float* b_out = (const float*)d_in[7];
    float* out = (float*)d_out;

    const int B = in_sizes[1];   // x0 element count

    lstm_mma_kernel<<<B / ROWS_CTA, NTH, SMEM_TOTAL>>>(
        x, x0, W_ih, W_hh, b_ih, b_hh, W_out, b_out, out);
}

// round 6
// speedup vs baseline: 1.4951x; 1.4951x over previous
#include <cuda_runtime.h>
#include <cuda_bf16.h>
#include <cstdint>

// LSTM B=65536, T=7, H=128, fused recurrence via warp-level mma.sync (bf16->f32).
// CTA = 512 thr / 16 warps / 64 batch rows, split into TWO INDEPENDENT GROUPS
// of 8 warps x 32 rows. Groups share only the read-only W' SMEM tile and sync
// via private named barriers (bar.sync 1/2), never CTA-wide -> one group's
// epilogue (MUFU/FMA) overlaps the other group's MMA phase (LDS/tensor).
// Per step: gates[32,512] = h[32,128] @ W'^T ; warp = 32 rows x 64 permuted
// cols (units w*16..w*16+15), K=128, fp32 accum (64 regs). W' rows j=u*4+g.

#define T 7
#define MTILE 64
#define NTH 512
#define WSTR 136   // bf16 elems per W' row (17x16B pitch -> ldmatrix conflict-free)
#define HSTR 136

#define W_OFF   0u
#define H0_OFF  139264u               // 512*136*2
#define H1_OFF  156672u               // +64*136*2
#define F32_OFF 174080u               // +64*136*2
#define F_BIAS 0
#define F_WIH  512
#define F_WOUT 1024
#define F_XS   1152                   // 64 rows x 8 slots
#define F_PRED 1664                   // 2 x (64 rows x 8 col-warps)
#define F_COUNT 2688
#define SMEM_TOTAL (174080 + F_COUNT * 4)   // 184832

static __device__ __forceinline__ uint32_t smem_u32(const void* p) {
    uint32_t a;
    asm("{ .reg .u64 t; cvta.to.shared.u64 t, %1; cvt.u32.u64 %0, t; }"
        : "=r"(a) : "l"(p));
    return a;
}
static __device__ __forceinline__ float tanh_fast(float v) {
    float y; asm("tanh.approx.f32 %0, %1;" : "=f"(y) : "f"(v)); return y;
}
static __device__ __forceinline__ float sigmoid_fast(float v) {
    return 0.5f * tanh_fast(0.5f * v) + 0.5f;
}
static __device__ __forceinline__ uint32_t pack_bf16x2(float lo, float hi) {
    uint32_t r;
    asm("cvt.rn.bf16x2.f32 %0, %1, %2;" : "=r"(r) : "f"(hi), "f"(lo));
    return r;
}

#define LDSM_X4(r0, r1, r2, r3, addr) \
    asm volatile("ldmatrix.sync.aligned.m8n8.x4.shared.b16 {%0,%1,%2,%3}, [%4];" \
        : "=r"(r0), "=r"(r1), "=r"(r2), "=r"(r3) : "r"(addr))

#define MMA16816(D, A, B0, B1) \
    asm volatile("mma.sync.aligned.m16n8k16.row.col.f32.bf16.bf16.f32 " \
        "{%0,%1,%2,%3}, {%4,%5,%6,%7}, {%8,%9}, {%0,%1,%2,%3};" \
        : "+f"((D)[0]), "+f"((D)[1]), "+f"((D)[2]), "+f"((D)[3]) \
        : "r"((A)[0]), "r"((A)[1]), "r"((A)[2]), "r"((A)[3]), "r"(B0), "r"(B1))

__global__ __launch_bounds__(NTH, 1)
void lstm_mma_kernel(const float* __restrict__ x,
                     const float* __restrict__ x0,
                     const float* __restrict__ W_ih,
                     const float* __restrict__ W_hh,
                     const float* __restrict__ b_ih,
                     const float* __restrict__ b_hh,
                     const float* __restrict__ W_out,
                     const float* __restrict__ b_out,
                     float* __restrict__ out)
{
    extern __shared__ char smem[];
    const uint32_t sb = smem_u32(smem);
    float* f32s = (float*)(smem + F32_OFF);

    const int tid  = threadIdx.x;
    const int wid  = tid >> 5;        // 0..15
    const int grp  = wid >> 3;        // 0/1: independent 32-row group
    const int gwid = wid & 7;         // col-warp within group: units gwid*16..+15
    const int lane = tid & 31;
    const int q    = lane & 3;
    const int par  = q & 1;           // gate-pair parity (row +0 / +8 after swap)
    const int hu   = q >> 1;          // unit-within-pair select
    const int rowBase = blockIdx.x * MTILE;

    // ---- one-time staging (full CTA) ----
    // W' rows j = u*4+g  <- W_hh row g*128+u, bf16, pitch WSTR
#pragma unroll
    for (int it = 0; it < 32; it++) {
        int idx = tid + it * NTH;            // 0..16383
        int j   = idx >> 5;                  // 0..511
        int kq  = (idx & 31) * 4;            // 0..124
        int src = (j & 3) * 128 + (j >> 2);
        float4 w4 = *(const float4*)(W_hh + src * 128 + kq);
        uint32_t o = (uint32_t)(j * WSTR + kq) * 2;
        *(uint32_t*)(smem + o)     = pack_bf16x2(w4.x, w4.y);
        *(uint32_t*)(smem + o + 4) = pack_bf16x2(w4.z, w4.w);
    }
    for (int i = tid; i < (int)(64 * HSTR * 2 / 4); i += NTH)   // zero h(par0)
        *(uint32_t*)(smem + H0_OFF + i * 4) = 0u;
    for (int j = tid; j < 512; j += NTH) {                      // permuted bias/W_ih
        int u = j >> 2, g = j & 3, src = g * 128 + u;
        f32s[F_BIAS + j] = b_ih[src] + b_hh[src];
        f32s[F_WIH + j]  = W_ih[src];
    }
    if (tid < 128) f32s[F_WOUT + tid] = W_out[tid];
    {   // tid covers exactly 64 rows x 8 slots
        int row = tid >> 3, sl = tid & 7;
        f32s[F_XS + tid] = (sl == 0) ? x0[rowBase + row]
                                     : x[(rowBase + row) * T + (sl > 6 ? 6 : sl - 1)];
    }
    __syncthreads();   // last CTA-wide barrier; groups free-run from here

    const float bout = b_out[0];

    float cst[2][8];   // [mi][nt] cell state for this thread's (row, unit) cells
#pragma unroll
    for (int mi = 0; mi < 2; mi++)
#pragma unroll
        for (int nt = 0; nt < 8; nt++) cst[mi][nt] = 0.0f;

    // per-thread ldmatrix byte offsets
    const uint32_t aOff = (uint32_t)(((lane & 15) * HSTR + ((lane >> 4) & 1) * 8) * 2);
    const uint32_t bOff = (uint32_t)(((gwid * 64 + ((lane >> 4) & 1) * 8 + (lane & 7)) * WSTR
                                      + ((lane >> 3) & 1) * 8) * 2);
    const int rowIn = (lane >> 2) + par * 8;     // row within a 16-row m-tile
    const int gtid  = tid & 255;                 // thread id within group
    const int barid = grp + 1;

    for (int s = 0; s < T; s++) {
        const uint32_t hcur = (s & 1) ? H1_OFF : H0_OFF;
        const uint32_t hnxt = (s & 1) ? H0_OFF : H1_OFF;

        float acc[2][8][4];
#pragma unroll
        for (int mi = 0; mi < 2; mi++)
#pragma unroll
            for (int nt = 0; nt < 8; nt++)
#pragma unroll
                for (int e = 0; e < 4; e++) acc[mi][nt][e] = 0.0f;

        // ---- MMA phase: rows grp*32 .. grp*32+31, K = 8 chunks of 16 ----
#pragma unroll
        for (int kc = 0; kc < 8; kc++) {
            uint32_t a[2][4];
#pragma unroll
            for (int mi = 0; mi < 2; mi++)
                LDSM_X4(a[mi][0], a[mi][1], a[mi][2], a[mi][3],
                        sb + hcur + aOff +
                        (uint32_t)(((grp * 32 + mi * 16) * HSTR + kc * 16) * 2));
#pragma unroll
            for (int np = 0; np < 4; np++) {
                uint32_t b0, b1, b2, b3;
                LDSM_X4(b0, b1, b2, b3,
                        sb + W_OFF + bOff + (uint32_t)((np * 16 * WSTR + kc * 16) * 2));
#pragma unroll
                for (int mi = 0; mi < 2; mi++) {
                    MMA16816(acc[mi][np * 2],     a[mi], b0, b1);
                    MMA16816(acc[mi][np * 2 + 1], a[mi], b2, b3);
                }
            }
        }

        // ---- epilogue ----
        const int pb = F_PRED + (s & 1) * 512;
#pragma unroll
        for (int mi = 0; mi < 2; mi++) {
            const int row_eff = grp * 32 + mi * 16 + rowIn;    // 0..63
            const float xv = f32s[F_XS + row_eff * 8 + s];
            float pred = 0.0f;
#pragma unroll
            for (int nt = 0; nt < 8; nt++) {
                // gate swap within lane pair (q even holds i,f; q odd holds g,o)
                float s0 = par ? acc[mi][nt][0] : acc[mi][nt][2];
                float s1 = par ? acc[mi][nt][1] : acc[mi][nt][3];
                float r0 = __shfl_xor_sync(0xffffffffu, s0, 1);
                float r1 = __shfl_xor_sync(0xffffffffu, s1, 1);
                float gi = par ? r0 : acc[mi][nt][0];
                float gf = par ? r1 : acc[mi][nt][1];
                float gg = par ? acc[mi][nt][2] : r0;
                float go = par ? acc[mi][nt][3] : r1;

                const int u = gwid * 16 + nt * 2 + hu;         // unit 0..127
                const float4 b4 = *(const float4*)&f32s[F_BIAS + u * 4];
                const float4 w4 = *(const float4*)&f32s[F_WIH + u * 4];
                gi += b4.x + xv * w4.x;
                gf += b4.y + xv * w4.y;
                gg += b4.z + xv * w4.z;
                go += b4.w + xv * w4.w;

                float ig = sigmoid_fast(gi);
                float fg = sigmoid_fast(gf);
                float g_ = tanh_fast(gg);
                float og = sigmoid_fast(go);
                float cn = fg * cst[mi][nt] + ig * g_;
                cst[mi][nt] = cn;
                float hn = og * tanh_fast(cn);
                pred += hn * f32s[F_WOUT + u];

                *(__nv_bfloat16*)(smem + hnxt + (uint32_t)((row_eff * HSTR + u) * 2)) =
                    __float2bfloat16(hn);
            }
            pred += __shfl_xor_sync(0xffffffffu, pred, 2);     // combine unit halves
            if (q < 2) f32s[pb + row_eff * 8 + gwid] = pred;
        }

        // group-private barrier: h(next) + pred partials visible to OWN group
        asm volatile("bar.sync %0, %1;" :: "r"(barid), "r"(256) : "memory");

        if (gtid < 32) {
            const int row = grp * 32 + gtid;
            float p = bout;
            const float* pp = &f32s[pb + row * 8];
#pragma unroll
            for (int w = 0; w < 8; w++) p += pp[w];
            out[(rowBase + row) * T + s] = p;
        }
    }
}

extern "C" void kernel_launch(void* const* d_in, const int* in_sizes, int n_in,
                              void* d_out, int out_size)
{
    const float* x     = (const float*)d_in[0];
    const float* x0    = (const float*)d_in[1];
    const float* W_ih  = (const float*)d_in[2];
    const float* W_hh  = (const float*)d_in[3];
    const float* b_ih  = (const float*)d_in[4];
    const float* b_hh  = (const float*)d_in[5];
    const float* W_out = (const float*)d_in[6];
    const float* b_out = (const float*)d_in[7];
    float* out = (float*)d_out;

    const int B = in_sizes[1];   // x0 element count

    cudaFuncSetAttribute(lstm_mma_kernel,
                         cudaFuncAttributeMaxDynamicSharedMemorySize, SMEM_TOTAL);

    lstm_mma_kernel<<<B / MTILE, NTH, SMEM_TOTAL>>>(
        x, x0, W_ih, W_hh, b_ih, b_hh, W_out, b_out, out);
}